// round 1
// baseline (speedup 1.0000x reference)
#include <cuda_runtime.h>

#define BB 2
#define DD 128
#define OD 123   // 128 - 6 + 1

// scratch: dense grid [B,128,128,128,3] + pad for edge-lane overreads
__device__ float g_dense[BB*DD*DD*DD*3 + 1024];
// composed weights, layout [sz][sy][i][o][sx]  (sx innermost for LDS.64 pairs)
__device__ float g_weff[6*6*6*3*3];

static __device__ __forceinline__ unsigned long long pack2(float lo, float hi) {
    unsigned long long r;
    asm("mov.b64 %0, {%1, %2};" : "=l"(r) : "f"(lo), "f"(hi));
    return r;
}
static __device__ __forceinline__ void fma2(unsigned long long &d,
                                            unsigned long long a,
                                            unsigned long long b) {
    asm("fma.rn.f32x2 %0, %1, %2, %0;" : "+l"(d) : "l"(a), "l"(b));
}
static __device__ __forceinline__ float2 unpack2(unsigned long long v) {
    float2 f;
    asm("mov.b64 {%0, %1}, %2;" : "=f"(f.x), "=f"(f.y) : "l"(v));
    return f;
}

__global__ void zero_kernel(int n4) {
    int i = blockIdx.x * blockDim.x + threadIdx.x;
    float4* p = (float4*)g_dense;
    float4 z = make_float4(0.f, 0.f, 0.f, 0.f);
    for (; i < n4; i += gridDim.x * blockDim.x) p[i] = z;
}

__global__ void scatter_kernel(const int* __restrict__ coords,
                               const float* __restrict__ voxels, int n) {
    int i = blockIdx.x * blockDim.x + threadIdx.x;
    if (i >= n) return;
    int b = coords[4*i+0], z = coords[4*i+1], y = coords[4*i+2], x = coords[4*i+3];
    int base = (((b*DD + z)*DD + y)*DD + x) * 3;
    atomicAdd(&g_dense[base+0], voxels[3*i+0]);
    atomicAdd(&g_dense[base+1], voxels[3*i+1]);
    atomicAdd(&g_dense[base+2], voxels[3*i+2]);
}

// Compose Weff = W1 (*) W2 (*) W3  (correlation composition; all linear)
__global__ void weff_kernel(const float* __restrict__ W1,
                            const float* __restrict__ W2,
                            const float* __restrict__ W3) {
    __shared__ float W12[4*4*4*3*5];   // [uz][uy][ux][i][m]
    int tid = threadIdx.x;
    for (int idx = tid; idx < 960; idx += blockDim.x) {
        int m = idx % 5, i = (idx/5) % 3, u = idx / 15;
        int ux = u % 4, uy = (u/4) % 4, uz = u / 16;
        float s = 0.f;
        for (int qz = 0; qz < 2; qz++) { int rz = uz - qz; if (rz < 0 || rz > 2) continue;
        for (int qy = 0; qy < 2; qy++) { int ry = uy - qy; if (ry < 0 || ry > 2) continue;
        for (int qx = 0; qx < 2; qx++) { int rx = ux - qx; if (rx < 0 || rx > 2) continue;
            const float* w1 = W1 + ((qz*2+qy)*2+qx)*27 + i*9;      // [.,i,c]
            const float* w2 = W2 + ((rz*3+ry)*3+rx)*45 + m;        // [.,c,m]
            for (int c = 0; c < 9; c++) s += w1[c] * w2[c*5];
        }}}
        W12[idx] = s;
    }
    __syncthreads();
    for (int idx = tid; idx < 5832; idx += blockDim.x) {
        int o = idx % 3, i = (idx/3) % 3, sp = idx / 9;
        int sx = sp % 6, sy = (sp/6) % 6, sz = sp / 36;
        float s = 0.f;
        for (int uz = 0; uz < 4; uz++) { int tz = sz - uz; if (tz < 0 || tz > 2) continue;
        for (int uy = 0; uy < 4; uy++) { int ty = sy - uy; if (ty < 0 || ty > 2) continue;
        for (int ux = 0; ux < 4; ux++) { int tx = sx - ux; if (tx < 0 || tx > 2) continue;
            const float* w12 = W12 + ((uz*4+uy)*4+ux)*15 + i*5;    // [.,i,m]
            const float* w3  = W3  + ((tz*3+ty)*3+tx)*15 + o;      // [.,m,o]
            for (int m = 0; m < 5; m++) s += w12[m] * w3[m*3];
        }}}
        g_weff[(((sz*6+sy)*3+i)*3+o)*6 + sx] = s;
    }
}

// Fused gather conv: out = relu(dense (*) Weff + b3)
// block: 128 threads = 32 x-groups * 4 y-rows; thread computes RX=4 x outputs * 3 ch
__global__ void __launch_bounds__(128) conv_kernel(const float* __restrict__ b3,
                                                   float* __restrict__ out) {
    __shared__ float Wsm[5832];
    for (int idx = threadIdx.x; idx < 5832; idx += 128) Wsm[idx] = g_weff[idx];
    __syncthreads();

    int tx = threadIdx.x & 31, ty = threadIdx.x >> 5;
    int y  = blockIdx.y * 4 + ty;
    int zb = blockIdx.z;
    int b  = zb / OD, z = zb - b * OD;
    int x0 = tx * 4;
    if (y >= OD || x0 >= OD) return;

    unsigned long long acc[4][3];
    #pragma unroll
    for (int rx = 0; rx < 4; rx++)
        #pragma unroll
        for (int o = 0; o < 3; o++) acc[rx][o] = 0ULL;

    const float* base = g_dense + ((b*DD + z)*DD + y)*(DD*3) + x0*3;  // 16B aligned

    #pragma unroll 1
    for (int sz = 0; sz < 6; sz++) {
      #pragma unroll 1
      for (int sy = 0; sy < 6; sy++) {
        const float* p = base + (sz*DD + sy)*(DD*3);
        float in[28];
        #pragma unroll
        for (int t = 0; t < 7; t++) {                 // 28 contiguous floats (x,ch)
            float4 v = *(const float4*)(p + 4*t);
            in[4*t+0] = v.x; in[4*t+1] = v.y; in[4*t+2] = v.z; in[4*t+3] = v.w;
        }
        const float* wr = Wsm + ((sz*6+sy)*3)*18;     // [i][o][sx]
        #pragma unroll
        for (int i = 0; i < 3; i++) {
          unsigned long long q[8];                    // q[k] = {x=k, x=k+1} at ch i
          #pragma unroll
          for (int k = 0; k < 8; k++) q[k] = pack2(in[k*3+i], in[k*3+3+i]);
          #pragma unroll
          for (int o = 0; o < 3; o++) {
            const float* w = wr + (i*3+o)*6;          // 8B-aligned rows of 6
            unsigned long long w01 = *(const unsigned long long*)(w);
            unsigned long long w23 = *(const unsigned long long*)(w+2);
            unsigned long long w45 = *(const unsigned long long*)(w+4);
            #pragma unroll
            for (int rx = 0; rx < 4; rx++) {
              fma2(acc[rx][o], q[rx+0], w01);         // sx = 0,1
              fma2(acc[rx][o], q[rx+2], w23);         // sx = 2,3
              fma2(acc[rx][o], q[rx+4], w45);         // sx = 4,5
            }
          }
        }
      }
    }

    float bias0 = b3[0], bias1 = b3[1], bias2 = b3[2];
    int ob = ((b*OD + z)*OD + y)*OD;
    #pragma unroll
    for (int rx = 0; rx < 4; rx++) {
        int x = x0 + rx;
        if (x >= OD) break;
        float2 f0 = unpack2(acc[rx][0]);
        float2 f1 = unpack2(acc[rx][1]);
        float2 f2 = unpack2(acc[rx][2]);
        out[(ob + x)*3 + 0] = fmaxf(f0.x + f0.y + bias0, 0.f);
        out[(ob + x)*3 + 1] = fmaxf(f1.x + f1.y + bias1, 0.f);
        out[(ob + x)*3 + 2] = fmaxf(f2.x + f2.y + bias2, 0.f);
    }
}

extern "C" void kernel_launch(void* const* d_in, const int* in_sizes, int n_in,
                              void* d_out, int out_size) {
    const int*   coords = (const int*)d_in[0];
    const float* voxels = (const float*)d_in[1];
    const float* W1 = (const float*)d_in[2];
    const float* W2 = (const float*)d_in[3];
    const float* W3 = (const float*)d_in[4];
    const float* b3 = (const float*)d_in[5];
    float* out = (float*)d_out;

    int n = in_sizes[0] / 4;   // coords is [N,4]

    int n4 = (BB*DD*DD*DD*3 + 1024) / 4;
    zero_kernel<<<1024, 256>>>(n4);
    scatter_kernel<<<(n + 255) / 256, 256>>>(coords, voxels, n);
    weff_kernel<<<1, 256>>>(W1, W2, W3);
    conv_kernel<<<dim3(1, (OD + 3) / 4, OD * BB), 128>>>(b3, out);
}